// round 4
// baseline (speedup 1.0000x reference)
#include <cuda_runtime.h>
#include <cuda_fp16.h>
#include <cstdint>
#include <cstddef>

// ---------------- problem constants ----------------
#define BB    128
#define TT    512
#define II    300
#define HH    150
#define G3    450    // 3H
#define D2    300    // 2H
#define KK    6
#define THD   20
#define CLSN  5

// ---------------- device scratch (static, allocation-free) ----------------
__device__ float g_gi[(size_t)2 * BB * TT * G3];    // [dir][b][t][g]  236MB
__device__ float g_seq[(size_t)BB * TT * D2];       // [b][t][d]       79MB
__device__ float g_hidden[BB * D2];
__device__ float g_ctxA[KK * D2];
__device__ float g_context[BB * KK * D2];
__device__ float g_energy[(size_t)BB * TT * KK];    // energy, then probs in-place
__device__ float g_pooled[BB * KK * D2];
__device__ float g_regb[BB];

// ==========================================================================
// K1: gi GEMM  — C[m,n] = x[m,:] . W[n,:] + bias[n]
//     m in [0,65536) = b*512+t ;  n in [0,900): n<450 -> forward, else backward
// ==========================================================================
#define BM 64
#define BN 64
#define BKK 16
__global__ void __launch_bounds__(256) gi_gemm(
    const float* __restrict__ x,
    const float* __restrict__ Wf, const float* __restrict__ Wb,
    const float* __restrict__ bf, const float* __restrict__ bb)
{
    __shared__ float As[BKK][BM];
    __shared__ float Bs[BKK][BN];

    const int m0 = blockIdx.x * BM;
    const int n0 = blockIdx.y * BN;
    const int tid = threadIdx.x;

    const int lr  = tid >> 2;        // 0..63
    const int lc4 = (tid & 3) * 4;   // 0,4,8,12

    const int tm = (tid >> 4) * 4;
    const int tn = (tid & 15) * 4;

    float acc[4][4];
    #pragma unroll
    for (int i = 0; i < 4; i++)
        #pragma unroll
        for (int j = 0; j < 4; j++) acc[i][j] = 0.f;

    const int nB = n0 + lr;
    const float* wrow = (nB < 450) ? (Wf + (size_t)nB * II)
                                   : (Wb + (size_t)(nB - 450) * II);
    const bool nvalid = (nB < 900);
    const float* arow = x + (size_t)(m0 + lr) * II;

    for (int kt = 0; kt < 19; kt++) {
        const int k0 = kt * BKK;
        // load A tile (transposed into As[k][m])
        if (k0 + lc4 + 3 < II) {
            float4 av = *(const float4*)(arow + k0 + lc4);
            As[lc4 + 0][lr] = av.x; As[lc4 + 1][lr] = av.y;
            As[lc4 + 2][lr] = av.z; As[lc4 + 3][lr] = av.w;
        } else {
            #pragma unroll
            for (int i = 0; i < 4; i++) {
                int k = k0 + lc4 + i;
                As[lc4 + i][lr] = (k < II) ? arow[k] : 0.f;
            }
        }
        // load B tile (W row-major, K contiguous)
        if (nvalid && (k0 + lc4 + 3 < II)) {
            float4 bv = *(const float4*)(wrow + k0 + lc4);
            Bs[lc4 + 0][lr] = bv.x; Bs[lc4 + 1][lr] = bv.y;
            Bs[lc4 + 2][lr] = bv.z; Bs[lc4 + 3][lr] = bv.w;
        } else {
            #pragma unroll
            for (int i = 0; i < 4; i++) {
                int k = k0 + lc4 + i;
                Bs[lc4 + i][lr] = (nvalid && k < II) ? wrow[k] : 0.f;
            }
        }
        __syncthreads();
        #pragma unroll
        for (int k = 0; k < BKK; k++) {
            float4 a = *(const float4*)&As[k][tm];
            float4 b = *(const float4*)&Bs[k][tn];
            float av[4] = {a.x, a.y, a.z, a.w};
            float bv[4] = {b.x, b.y, b.z, b.w};
            #pragma unroll
            for (int i = 0; i < 4; i++)
                #pragma unroll
                for (int j = 0; j < 4; j++)
                    acc[i][j] += av[i] * bv[j];
        }
        __syncthreads();
    }

    #pragma unroll
    for (int i = 0; i < 4; i++) {
        const int m = m0 + tm + i;
        const int b = m >> 9;
        const int t = m & 511;
        #pragma unroll
        for (int j = 0; j < 4; j++) {
            const int n = n0 + tn + j;
            if (n < 900) {
                const int dir = (n >= 450);
                const int g = n - dir * 450;
                const float bias = dir ? bb[g] : bf[g];
                g_gi[(((size_t)(dir * BB + b)) * TT + t) * G3 + g] = acc[i][j] + bias;
            }
        }
    }
}

// ==========================================================================
// K2: GRU scan.  128 CTAs, each owns (dir, batch-pair), 512 sequential steps.
//     Whh in smem as fp16 in chunk-major layout (conflict-free LDS.128),
//     h in fp16 for HFMA2 matvec + fp32 master copy for gating.
// ==========================================================================
#define NCHUNK 19              // 19 chunks * 8 halves = 152 (150 + 2 pad)
#define OFF_BHH   136800       // 19*450*16
#define OFF_HH    138608       // aligned 16
#define OFF_HF    139216
#define OFF_GH    140416
#define GRU_SMEM  144016

__global__ void __launch_bounds__(512) gru_scan(
    const float* __restrict__ Whh_f, const float* __restrict__ Whh_b,
    const float* __restrict__ bhh_f, const float* __restrict__ bhh_b)
{
    extern __shared__ unsigned char sm[];
    uint4*  Wsm   = (uint4*)sm;                    // [chunk][row] each uint4 = 8 halves
    float*  bhh_s = (float*)(sm + OFF_BHH);        // 450
    __half* hh    = (__half*)(sm + OFF_HH);        // [2][152]
    float*  hf    = (float*)(sm + OFF_HF);         // [2][150]
    float*  ghm   = (float*)(sm + OFF_GH);         // [2][450]

    const int tid = threadIdx.x;
    const int dir = blockIdx.x >> 6;
    const int b0  = (blockIdx.x & 63) * 2;
    const float* Whh = dir ? Whh_b : Whh_f;
    const float* bhh = dir ? bhh_b : bhh_f;

    for (int i = tid; i < G3; i += 512) bhh_s[i] = bhh[i];
    // convert weights to fp16, chunk-major layout
    for (int p = tid; p < G3 * 76; p += 512) {
        int r = p / 76, kp = p % 76;
        int k0 = kp * 2;
        float f0 = (k0     < HH) ? Whh[r * HH + k0]     : 0.f;
        float f1 = (k0 + 1 < HH) ? Whh[r * HH + k0 + 1] : 0.f;
        __half2 hv = __floats2half2_rn(f0, f1);
        int c = kp >> 2, lane = kp & 3;
        ((__half2*)(Wsm + (c * G3 + r)))[lane] = hv;
    }
    for (int i = tid; i < 2 * 152; i += 512) hh[i] = __float2half(0.f);
    if (tid < 300) hf[tid] = 0.f;
    __syncthreads();

    const int nb = tid / HH;     // valid when tid < 300
    const int j  = tid % HH;

    for (int s = 0; s < TT; s++) {
        const int t = dir ? (TT - 1 - s) : s;
        float gir = 0.f, giz = 0.f, gin = 0.f;
        if (tid < 300) {
            const float* gi = g_gi + (((size_t)(dir * BB + b0 + nb)) * TT + t) * G3;
            gir = gi[j]; giz = gi[HH + j]; gin = gi[2 * HH + j];
        }
        if (tid < G3) {
            const uint4* wr = Wsm + tid;
            const uint4* h0 = (const uint4*)(hh);
            const uint4* h1 = (const uint4*)(hh + 152);
            float acc0 = 0.f, acc1 = 0.f;
            #pragma unroll
            for (int c = 0; c < NCHUNK; c++) {
                uint4 w  = wr[c * G3];
                uint4 ha = h0[c];
                uint4 hb = h1[c];
                const __half2* wp  = (const __half2*)&w;
                const __half2* hap = (const __half2*)&ha;
                const __half2* hbp = (const __half2*)&hb;
                __half2 s0 = __floats2half2_rn(0.f, 0.f);
                __half2 s1 = s0;
                #pragma unroll
                for (int q = 0; q < 4; q++) {
                    s0 = __hfma2(wp[q], hap[q], s0);
                    s1 = __hfma2(wp[q], hbp[q], s1);
                }
                float2 f0 = __half22float2(s0); acc0 += f0.x + f0.y;
                float2 f1 = __half22float2(s1); acc1 += f1.x + f1.y;
            }
            const float bbv = bhh_s[tid];
            ghm[tid]      = acc0 + bbv;
            ghm[G3 + tid] = acc1 + bbv;
        }
        __syncthreads();
        if (tid < 300) {
            const float* gh = ghm + nb * G3;
            float r = 1.f / (1.f + __expf(-(gir + gh[j])));
            float z = 1.f / (1.f + __expf(-(giz + gh[HH + j])));
            float n = tanhf(gin + r * gh[2 * HH + j]);
            float h = hf[tid];
            float hn = (1.f - z) * n + z * h;
            hf[tid] = hn;
            hh[nb * 152 + j] = __float2half_rn(hn);
            g_seq[(((size_t)(b0 + nb)) * TT + t) * D2 + dir * HH + j] = hn;
        }
        __syncthreads();
    }
    if (tid < 300)
        g_hidden[(b0 + nb) * D2 + dir * HH + j] = hf[tid];
}

// ==========================================================================
// K3a0: ctxA[k][d] = battn[k][d] + attn_context[k,:] . Wattn[k][:300][d]
// ==========================================================================
__global__ void __launch_bounds__(320) ctxA_kernel(
    const float* __restrict__ attn_context, const float* __restrict__ Wattn,
    const float* __restrict__ battn)
{
    const int k = blockIdx.x;
    const int d = threadIdx.x;
    __shared__ float ac[D2];
    if (d < D2) ac[d] = attn_context[k * D2 + d];
    __syncthreads();
    if (d < D2) {
        float acc = battn[k * D2 + d];
        for (int c = 0; c < D2; c++)
            acc += ac[c] * Wattn[((size_t)k * 600 + c) * D2 + d];
        g_ctxA[k * D2 + d] = acc;
    }
}

// ==========================================================================
// K3a: context[b][k][d] = tanh(ctxA[k][d] + hidden[b,:] . Wattn[k][300:][d])
//      grid (k=6, btile=16 of 8 batches)
// ==========================================================================
__global__ void __launch_bounds__(320) context_kernel(const float* __restrict__ Wattn)
{
    const int k  = blockIdx.x;
    const int b0 = blockIdx.y * 8;
    const int d  = threadIdx.x;
    __shared__ float hid[8 * D2];
    for (int i = threadIdx.x; i < 8 * D2; i += blockDim.x) hid[i] = g_hidden[b0 * D2 + i];
    __syncthreads();
    if (d < D2) {
        float acc[8];
        const float base = g_ctxA[k * D2 + d];
        #pragma unroll
        for (int bb = 0; bb < 8; bb++) acc[bb] = base;
        for (int jj = 0; jj < D2; jj++) {
            const float w = Wattn[((size_t)k * 600 + D2 + jj) * D2 + d];
            #pragma unroll
            for (int bb = 0; bb < 8; bb++) acc[bb] += hid[bb * D2 + jj] * w;
        }
        #pragma unroll
        for (int bb = 0; bb < 8; bb++)
            g_context[((size_t)(b0 + bb) * KK + k) * D2 + d] = tanhf(acc[bb]);
    }
}

// ==========================================================================
// K3b: energy[b][t][k] = seq[b,t,:] . context[b,k,:]
// ==========================================================================
__global__ void __launch_bounds__(256) energy_kernel()
{
    const int b = blockIdx.x;
    __shared__ float ctx[KK * 301];
    __shared__ float seq_s[32 * D2];
    const int tid = threadIdx.x;
    for (int i = tid; i < KK * D2; i += 256) {
        int k = i / D2, d = i % D2;
        ctx[k * 301 + d] = g_context[((size_t)b * KK + k) * D2 + d];
    }
    const int tt = tid >> 3, kk = tid & 7;
    for (int t0 = 0; t0 < TT; t0 += 32) {
        __syncthreads();
        for (int i = tid; i < 32 * D2; i += 256)
            seq_s[i] = g_seq[((size_t)b * TT + t0) * D2 + i];
        __syncthreads();
        if (kk < KK) {
            const float* sr = seq_s + tt * D2;
            const float* cr = ctx + kk * 301;
            float e = 0.f;
            #pragma unroll 4
            for (int d = 0; d < D2; d++) e += sr[d] * cr[d];
            g_energy[((size_t)b * TT + t0 + tt) * KK + kk] = e;
        }
    }
}

// ==========================================================================
// K3c: softmax over T per (b,k), in place on g_energy
// ==========================================================================
__global__ void __launch_bounds__(192) softmax_t()
{
    const int b = blockIdx.x;
    const int k = threadIdx.x >> 5;
    const int lane = threadIdx.x & 31;
    float v[16];
    float m = -1e30f;
    #pragma unroll
    for (int i = 0; i < 16; i++) {
        v[i] = g_energy[((size_t)b * TT + lane + i * 32) * KK + k];
        m = fmaxf(m, v[i]);
    }
    #pragma unroll
    for (int o = 16; o; o >>= 1) m = fmaxf(m, __shfl_xor_sync(0xffffffffu, m, o));
    float ssum = 0.f;
    #pragma unroll
    for (int i = 0; i < 16; i++) { v[i] = __expf(v[i] - m); ssum += v[i]; }
    #pragma unroll
    for (int o = 16; o; o >>= 1) ssum += __shfl_xor_sync(0xffffffffu, ssum, o);
    const float inv = 1.f / ssum;
    #pragma unroll
    for (int i = 0; i < 16; i++)
        g_energy[((size_t)b * TT + lane + i * 32) * KK + k] = v[i] * inv;
}

// ==========================================================================
// K3d: pooled[b][k][d] = sum_t seq[b,t,d] * probs[b,t,k]
// ==========================================================================
__global__ void __launch_bounds__(320) pooled_kernel()
{
    const int b = blockIdx.x;
    const int tid = threadIdx.x;
    __shared__ float seq_s[32 * D2];
    __shared__ float pr[32 * 8];
    float acc[KK];
    #pragma unroll
    for (int k = 0; k < KK; k++) acc[k] = 0.f;
    for (int t0 = 0; t0 < TT; t0 += 32) {
        __syncthreads();
        for (int i = tid; i < 32 * D2; i += 320)
            seq_s[i] = g_seq[((size_t)b * TT + t0) * D2 + i];
        for (int i = tid; i < 32 * KK; i += 320) {
            int tt = i / KK, k = i % KK;
            pr[tt * 8 + k] = g_energy[((size_t)b * TT + t0 + tt) * KK + k];
        }
        __syncthreads();
        if (tid < D2) {
            #pragma unroll 4
            for (int tt = 0; tt < 32; tt++) {
                const float sv = seq_s[tt * D2 + tid];
                #pragma unroll
                for (int k = 0; k < KK; k++) acc[k] += sv * pr[tt * 8 + k];
            }
        }
    }
    if (tid < D2) {
        #pragma unroll
        for (int k = 0; k < KK; k++)
            g_pooled[((size_t)b * KK + k) * D2 + tid] = acc[k];
    }
}

// ==========================================================================
// K3e: topic heads + logits + softmax + per-batch reg term
// ==========================================================================
__global__ void __launch_bounds__(128) head_kernel(
    const float* __restrict__ Wtop, const float* __restrict__ btop,
    const float* __restrict__ Wout, const float* __restrict__ bout,
    float* __restrict__ out)
{
    const int b = blockIdx.x;
    const int tid = threadIdx.x;
    __shared__ float pl[KK * D2];
    __shared__ float cx[KK * D2];
    __shared__ float tp[KK * THD];
    __shared__ float lg[CLSN];
    __shared__ float inorm[KK];
    __shared__ float gsq[KK * KK];
    for (int i = tid; i < KK * D2; i += 128) {
        pl[i] = g_pooled[(size_t)b * KK * D2 + i];
        cx[i] = g_context[(size_t)b * KK * D2 + i];
    }
    __syncthreads();
    if (tid < KK * THD) {
        const int k = tid / THD, h = tid % THD;
        float a = btop[tid];
        const float* pk = pl + k * D2;
        for (int d = 0; d < D2; d++)
            a += pk[d] * Wtop[((size_t)k * D2 + d) * THD + h];
        tp[tid] = fmaxf(a, 0.f);
    }
    if (tid >= 120 && tid < 120 + KK) {
        const int k = tid - 120;
        const float* ck = cx + k * D2;
        float s = 0.f;
        for (int d = 0; d < D2; d++) s += ck[d] * ck[d];
        inorm[k] = 1.f / fmaxf(sqrtf(s), 1e-12f);
    }
    __syncthreads();
    if (tid < CLSN) {
        float L = bout[tid];
        for (int i = 0; i < KK * THD; i++) L += tp[i] * Wout[i * CLSN + tid];
        lg[tid] = L;
    }
    if (tid >= 32 && tid < 32 + KK * KK) {
        const int q = tid - 32;
        const int k = q / KK, j = q % KK;
        const float* ck = cx + k * D2;
        const float* cj = cx + j * D2;
        float gdot = 0.f;
        for (int d = 0; d < D2; d++) gdot += ck[d] * cj[d];
        gdot *= inorm[k] * inorm[j];
        const float diff = gdot - (k == j ? 1.f : 0.f);
        gsq[q] = diff * diff;
    }
    __syncthreads();
    if (tid < CLSN) {
        float m = lg[0];
        #pragma unroll
        for (int i = 1; i < CLSN; i++) m = fmaxf(m, lg[i]);
        float ss = 0.f;
        #pragma unroll
        for (int i = 0; i < CLSN; i++) ss += __expf(lg[i] - m);
        out[b * CLSN + tid] = __expf(lg[tid] - m) / ss;
    }
    if (tid == 0) {
        float ssum = 0.f;
        #pragma unroll
        for (int i = 0; i < KK * KK; i++) ssum += gsq[i];
        g_regb[b] = sqrtf(ssum);
    }
}

// ==========================================================================
// K3f: reg = mean_b(g_regb)
// ==========================================================================
__global__ void __launch_bounds__(128) reg_reduce(float* __restrict__ out, int out_size)
{
    __shared__ float sh[128];
    const int tid = threadIdx.x;
    sh[tid] = g_regb[tid];
    __syncthreads();
    for (int o = 64; o; o >>= 1) {
        if (tid < o) sh[tid] += sh[tid + o];
        __syncthreads();
    }
    if (tid == 0) out[out_size - 1] = sh[0] * (1.f / 128.f);
}

// ==========================================================================
extern "C" void kernel_launch(void* const* d_in, const int* in_sizes, int n_in,
                              void* d_out, int out_size)
{
    const float* x            = (const float*)d_in[0];
    const float* Wih_f        = (const float*)d_in[1];
    const float* Whh_f        = (const float*)d_in[2];
    const float* bih_f        = (const float*)d_in[3];
    const float* bhh_f        = (const float*)d_in[4];
    const float* Wih_b        = (const float*)d_in[5];
    const float* Whh_b        = (const float*)d_in[6];
    const float* bih_b        = (const float*)d_in[7];
    const float* bhh_b        = (const float*)d_in[8];
    const float* attn_context = (const float*)d_in[9];
    const float* Wattn        = (const float*)d_in[10];
    const float* battn        = (const float*)d_in[11];
    const float* Wtop         = (const float*)d_in[12];
    const float* btop         = (const float*)d_in[13];
    const float* Wout         = (const float*)d_in[14];
    const float* bout         = (const float*)d_in[15];
    float* out = (float*)d_out;

    cudaFuncSetAttribute(gru_scan, cudaFuncAttributeMaxDynamicSharedMemorySize, GRU_SMEM);

    gi_gemm<<<dim3((BB * TT) / BM, (900 + BN - 1) / BN), 256>>>(x, Wih_f, Wih_b, bih_f, bih_b);
    gru_scan<<<128, 512, GRU_SMEM>>>(Whh_f, Whh_b, bhh_f, bhh_b);
    ctxA_kernel<<<KK, 320>>>(attn_context, Wattn, battn);
    context_kernel<<<dim3(KK, 16), 320>>>(Wattn);
    energy_kernel<<<BB, 256>>>();
    softmax_t<<<BB, 192>>>();
    pooled_kernel<<<BB, 320>>>();
    head_kernel<<<BB, 128>>>(Wtop, btop, Wout, bout, out);
    reg_reduce<<<1, 128>>>(out, out_size);
}

// round 5
// speedup vs baseline: 1.5679x; 1.5679x over previous
#include <cuda_runtime.h>
#include <cuda_fp16.h>
#include <cstdint>
#include <cstddef>

// ---------------- problem constants ----------------
#define BB    128
#define TT    512
#define II    300
#define HH    150
#define G3    450    // 3H
#define D2    300    // 2H
#define KK    6
#define THD   20
#define CLSN  5

#define KP    320    // padded K for fp16 GEMM (300 -> 320)
#define NPAD  960    // padded N (900 -> 960)

// ---------------- device scratch (static, allocation-free) ----------------
__device__ float g_gi[(size_t)2 * BB * TT * G3];    // [dir][b][t][g]
__device__ float g_seq[(size_t)BB * TT * D2];       // [b][t][d]
__device__ float g_hidden[BB * D2];
__device__ float g_ctxA[KK * D2];
__device__ float g_context[BB * KK * D2];
__device__ float g_energy[(size_t)BB * TT * KK];    // energy, then probs in-place
__device__ float g_pooled[BB * KK * D2];
__device__ float g_regb[BB];
__device__ __half g_xh[(size_t)BB * TT * KP];       // fp16 x, K padded
__device__ __half g_wh[(size_t)NPAD * KP];          // fp16 [Wf;Wb], K padded

// ==========================================================================
// K0a/K0b: fp32 -> fp16 conversion (zero-padded K)
// ==========================================================================
__global__ void __launch_bounds__(256) cvt_x(const float* __restrict__ x)
{
    size_t i = (size_t)blockIdx.x * 256 + threadIdx.x;
    if (i >= (size_t)BB * TT * KP) return;
    int col = (int)(i % KP);
    size_t row = i / KP;
    g_xh[i] = (col < II) ? __float2half_rn(x[row * II + col]) : __float2half(0.f);
}

__global__ void __launch_bounds__(256) cvt_w(const float* __restrict__ Wf,
                                             const float* __restrict__ Wb)
{
    int i = blockIdx.x * 256 + threadIdx.x;
    if (i >= NPAD * KP) return;
    int col = i % KP;
    int row = i / KP;
    float v = 0.f;
    if (col < II && row < 900)
        v = (row < 450) ? Wf[row * II + col] : Wb[(row - 450) * II + col];
    g_wh[i] = __float2half_rn(v);
}

// ==========================================================================
// K1: gi GEMM on tensor cores (mma.sync m16n8k16, fp16 in / fp32 accum)
//     C[m,n] = xh[m,:] . wh[n,:] + bias[n]
//     block tile 128x64x32, 8 warps (4m x 2n), warp tile 32x32
// ==========================================================================
__device__ __forceinline__ uint32_t s2u(const void* p) {
    return (uint32_t)__cvta_generic_to_shared(p);
}

#define LDSM4(R, addr) \
    asm volatile("ldmatrix.sync.aligned.m8n8.x4.shared.b16 {%0,%1,%2,%3}, [%4];" \
        : "=r"((R)[0]), "=r"((R)[1]), "=r"((R)[2]), "=r"((R)[3]) : "r"(addr))

#define MMA16816(C, A, b0, b1) \
    asm volatile("mma.sync.aligned.m16n8k16.row.col.f32.f16.f16.f32 " \
        "{%0,%1,%2,%3},{%4,%5,%6,%7},{%8,%9},{%0,%1,%2,%3};" \
        : "+f"((C)[0]), "+f"((C)[1]), "+f"((C)[2]), "+f"((C)[3]) \
        : "r"((A)[0]), "r"((A)[1]), "r"((A)[2]), "r"((A)[3]), "r"(b0), "r"(b1))

#define GBM 128
#define GBN 64
#define GBK 32
#define SPAD 40      // smem row stride in halves (80B: conflict-free ldmatrix)

__global__ void __launch_bounds__(256) gi_gemm_mma(
    const float* __restrict__ bf, const float* __restrict__ bb)
{
    __shared__ __half As[2][GBM][SPAD];
    __shared__ __half Bs[2][GBN][SPAD];

    const int tid  = threadIdx.x;
    const int m0   = blockIdx.x * GBM;
    const int n0   = blockIdx.y * GBN;
    const int warp = tid >> 5;
    const int lane = tid & 31;
    const int wm   = (warp >> 1) * 32;   // 0,32,64,96
    const int wn   = (warp & 1) * 32;    // 0,32

    // global load mapping: A tile = 512 uint4 (2/thread), B tile = 256 uint4
    const int gr = tid >> 2;            // 0..63
    const int gc = (tid & 3) * 8;       // half offset
    const __half* aP0 = g_xh + (size_t)(m0 + gr) * KP + gc;
    const __half* aP1 = g_xh + (size_t)(m0 + gr + 64) * KP + gc;
    const __half* bP  = g_wh + (size_t)(n0 + gr) * KP + gc;

    // ldmatrix base addresses (buf 0)
    const uint32_t aAddr = s2u(&As[0][wm + (lane & 15)][(lane >> 4) * 8]);
    const uint32_t bAddr = s2u(&Bs[0][wn + ((lane >> 4) << 3) + (lane & 7)][((lane >> 3) & 1) * 8]);
    const uint32_t ABUF = GBM * SPAD * 2;   // 10240
    const uint32_t BBUF = GBN * SPAD * 2;   // 5120
    const uint32_t RSTR = SPAD * 2;         // 80 bytes / row

    float acc[2][4][4];
    #pragma unroll
    for (int i = 0; i < 2; i++)
        #pragma unroll
        for (int j = 0; j < 4; j++)
            #pragma unroll
            for (int q = 0; q < 4; q++) acc[i][j][q] = 0.f;

    // prologue: tile 0
    uint4 ra0 = *(const uint4*)aP0;
    uint4 ra1 = *(const uint4*)aP1;
    uint4 rb  = *(const uint4*)bP;
    *(uint4*)&As[0][gr][gc]      = ra0;
    *(uint4*)&As[0][gr + 64][gc] = ra1;
    *(uint4*)&Bs[0][gr][gc]      = rb;
    __syncthreads();

    const int NKT = KP / GBK;   // 10
    for (int kt = 0; kt < NKT; kt++) {
        const int buf = kt & 1;
        if (kt < NKT - 1) {
            const size_t off = (size_t)(kt + 1) * GBK;
            ra0 = *(const uint4*)(aP0 + off);
            ra1 = *(const uint4*)(aP1 + off);
            rb  = *(const uint4*)(bP + off);
        }
        #pragma unroll
        for (int ks = 0; ks < 2; ks++) {
            uint32_t A0[4], A1[4], B0[4], B1[4];
            const uint32_t ao = aAddr + buf * ABUF + ks * 32;
            const uint32_t bo = bAddr + buf * BBUF + ks * 32;
            LDSM4(A0, ao);
            LDSM4(A1, ao + 16 * RSTR);
            LDSM4(B0, bo);
            LDSM4(B1, bo + 16 * RSTR);
            MMA16816(acc[0][0], A0, B0[0], B0[1]);
            MMA16816(acc[0][1], A0, B0[2], B0[3]);
            MMA16816(acc[0][2], A0, B1[0], B1[1]);
            MMA16816(acc[0][3], A0, B1[2], B1[3]);
            MMA16816(acc[1][0], A1, B0[0], B0[1]);
            MMA16816(acc[1][1], A1, B0[2], B0[3]);
            MMA16816(acc[1][2], A1, B1[0], B1[1]);
            MMA16816(acc[1][3], A1, B1[2], B1[3]);
        }
        if (kt < NKT - 1) {
            const int nb = buf ^ 1;
            *(uint4*)&As[nb][gr][gc]      = ra0;
            *(uint4*)&As[nb][gr + 64][gc] = ra1;
            *(uint4*)&Bs[nb][gr][gc]      = rb;
        }
        __syncthreads();
    }

    // epilogue: scatter to g_gi with bias
    const int cr = lane >> 2;           // row within 8
    const int cc = (lane & 3) * 2;      // col pair
    #pragma unroll
    for (int mi = 0; mi < 2; mi++) {
        #pragma unroll
        for (int ni = 0; ni < 4; ni++) {
            const int n = n0 + wn + ni * 8 + cc;
            if (n + 1 < 900) {
                const int dir = (n >= 450);
                const int g   = n - dir * 450;
                const float b0v = dir ? bb[g]     : bf[g];
                const float b1v = dir ? bb[g + 1] : bf[g + 1];
                const size_t dbase = (size_t)dir * BB * TT * G3;
                const int m = m0 + wm + mi * 16 + cr;
                float* p0 = g_gi + dbase + (size_t)m * G3 + g;
                float* p1 = g_gi + dbase + (size_t)(m + 8) * G3 + g;
                p0[0] = acc[mi][ni][0] + b0v;
                p0[1] = acc[mi][ni][1] + b1v;
                p1[0] = acc[mi][ni][2] + b0v;
                p1[1] = acc[mi][ni][3] + b1v;
            }
        }
    }
}

// ==========================================================================
// K2: GRU scan.  128 CTAs, each owns (dir, batch-pair), 512 sequential steps.
// ==========================================================================
#define NCHUNK 19              // 19 chunks * 8 halves = 152 (150 + 2 pad)
#define OFF_BHH   136800       // 19*450*16
#define OFF_HH    138608       // aligned 16
#define OFF_HF    139216
#define OFF_GH    140416
#define GRU_SMEM  144016

__global__ void __launch_bounds__(512) gru_scan(
    const float* __restrict__ Whh_f, const float* __restrict__ Whh_b,
    const float* __restrict__ bhh_f, const float* __restrict__ bhh_b)
{
    extern __shared__ unsigned char sm[];
    uint4*  Wsm   = (uint4*)sm;                    // [chunk][row] each uint4 = 8 halves
    float*  bhh_s = (float*)(sm + OFF_BHH);        // 450
    __half* hh    = (__half*)(sm + OFF_HH);        // [2][152]
    float*  hf    = (float*)(sm + OFF_HF);         // [2][150]
    float*  ghm   = (float*)(sm + OFF_GH);         // [2][450]

    const int tid = threadIdx.x;
    const int dir = blockIdx.x >> 6;
    const int b0  = (blockIdx.x & 63) * 2;
    const float* Whh = dir ? Whh_b : Whh_f;
    const float* bhh = dir ? bhh_b : bhh_f;

    for (int i = tid; i < G3; i += 512) bhh_s[i] = bhh[i];
    for (int p = tid; p < G3 * 76; p += 512) {
        int r = p / 76, kp = p % 76;
        int k0 = kp * 2;
        float f0 = (k0     < HH) ? Whh[r * HH + k0]     : 0.f;
        float f1 = (k0 + 1 < HH) ? Whh[r * HH + k0 + 1] : 0.f;
        __half2 hv = __floats2half2_rn(f0, f1);
        int c = kp >> 2, lane = kp & 3;
        ((__half2*)(Wsm + (c * G3 + r)))[lane] = hv;
    }
    for (int i = tid; i < 2 * 152; i += 512) hh[i] = __float2half(0.f);
    if (tid < 300) hf[tid] = 0.f;
    __syncthreads();

    const int nb = tid / HH;     // valid when tid < 300
    const int j  = tid % HH;

    for (int s = 0; s < TT; s++) {
        const int t = dir ? (TT - 1 - s) : s;
        float gir = 0.f, giz = 0.f, gin = 0.f;
        if (tid < 300) {
            const float* gi = g_gi + (((size_t)(dir * BB + b0 + nb)) * TT + t) * G3;
            gir = gi[j]; giz = gi[HH + j]; gin = gi[2 * HH + j];
        }
        if (tid < G3) {
            const uint4* wr = Wsm + tid;
            const uint4* h0 = (const uint4*)(hh);
            const uint4* h1 = (const uint4*)(hh + 152);
            float acc0 = 0.f, acc1 = 0.f;
            #pragma unroll
            for (int c = 0; c < NCHUNK; c++) {
                uint4 w  = wr[c * G3];
                uint4 ha = h0[c];
                uint4 hb = h1[c];
                const __half2* wp  = (const __half2*)&w;
                const __half2* hap = (const __half2*)&ha;
                const __half2* hbp = (const __half2*)&hb;
                __half2 s0 = __floats2half2_rn(0.f, 0.f);
                __half2 s1 = s0;
                #pragma unroll
                for (int q = 0; q < 4; q++) {
                    s0 = __hfma2(wp[q], hap[q], s0);
                    s1 = __hfma2(wp[q], hbp[q], s1);
                }
                float2 f0 = __half22float2(s0); acc0 += f0.x + f0.y;
                float2 f1 = __half22float2(s1); acc1 += f1.x + f1.y;
            }
            const float bbv = bhh_s[tid];
            ghm[tid]      = acc0 + bbv;
            ghm[G3 + tid] = acc1 + bbv;
        }
        __syncthreads();
        if (tid < 300) {
            const float* gh = ghm + nb * G3;
            float r = 1.f / (1.f + __expf(-(gir + gh[j])));
            float z = 1.f / (1.f + __expf(-(giz + gh[HH + j])));
            float n = tanhf(gin + r * gh[2 * HH + j]);
            float h = hf[tid];
            float hn = (1.f - z) * n + z * h;
            hf[tid] = hn;
            hh[nb * 152 + j] = __float2half_rn(hn);
            g_seq[(((size_t)(b0 + nb)) * TT + t) * D2 + dir * HH + j] = hn;
        }
        __syncthreads();
    }
    if (tid < 300)
        g_hidden[(b0 + nb) * D2 + dir * HH + j] = hf[tid];
}

// ==========================================================================
// K3a0: ctxA[k][d] = battn[k][d] + attn_context[k,:] . Wattn[k][:300][d]
// ==========================================================================
__global__ void __launch_bounds__(320) ctxA_kernel(
    const float* __restrict__ attn_context, const float* __restrict__ Wattn,
    const float* __restrict__ battn)
{
    const int k = blockIdx.x;
    const int d = threadIdx.x;
    __shared__ float ac[D2];
    if (d < D2) ac[d] = attn_context[k * D2 + d];
    __syncthreads();
    if (d < D2) {
        float acc = battn[k * D2 + d];
        const float* wp = Wattn + (size_t)k * 600 * D2 + d;
        #pragma unroll 1
        for (int c = 0; c < D2; c += 4) {
            float w0 = wp[(size_t)(c + 0) * D2];
            float w1 = wp[(size_t)(c + 1) * D2];
            float w2 = wp[(size_t)(c + 2) * D2];
            float w3 = wp[(size_t)(c + 3) * D2];
            acc += ac[c] * w0 + ac[c + 1] * w1 + ac[c + 2] * w2 + ac[c + 3] * w3;
        }
        g_ctxA[k * D2 + d] = acc;
    }
}

// ==========================================================================
// K3a: context[b][k][d] = tanh(ctxA[k][d] + hidden[b,:] . Wattn[k][300:][d])
//      grid (k=6, btile=32 of 4 batches); jj unrolled x4 for LDG ILP
// ==========================================================================
__global__ void __launch_bounds__(320) context_kernel(const float* __restrict__ Wattn)
{
    const int k  = blockIdx.x;
    const int b0 = blockIdx.y * 4;
    const int d  = threadIdx.x;
    __shared__ float hid[4 * D2];
    for (int i = threadIdx.x; i < 4 * D2; i += blockDim.x) hid[i] = g_hidden[b0 * D2 + i];
    __syncthreads();
    if (d < D2) {
        float acc[4];
        const float base = g_ctxA[k * D2 + d];
        #pragma unroll
        for (int bb = 0; bb < 4; bb++) acc[bb] = base;
        const float* wp = Wattn + ((size_t)k * 600 + D2) * D2 + d;
        #pragma unroll 1
        for (int jj = 0; jj < D2; jj += 4) {
            float w0 = wp[(size_t)(jj + 0) * D2];
            float w1 = wp[(size_t)(jj + 1) * D2];
            float w2 = wp[(size_t)(jj + 2) * D2];
            float w3 = wp[(size_t)(jj + 3) * D2];
            #pragma unroll
            for (int bb = 0; bb < 4; bb++) {
                acc[bb] += hid[bb * D2 + jj] * w0 + hid[bb * D2 + jj + 1] * w1
                         + hid[bb * D2 + jj + 2] * w2 + hid[bb * D2 + jj + 3] * w3;
            }
        }
        #pragma unroll
        for (int bb = 0; bb < 4; bb++)
            g_context[((size_t)(b0 + bb) * KK + k) * D2 + d] = tanhf(acc[bb]);
    }
}

// ==========================================================================
// K3b: energy[b][t][k] = seq[b,t,:] . context[b,k,:]
// ==========================================================================
__global__ void __launch_bounds__(256) energy_kernel()
{
    const int b = blockIdx.x;
    __shared__ float ctx[KK * 301];
    __shared__ float seq_s[32 * D2];
    const int tid = threadIdx.x;
    for (int i = tid; i < KK * D2; i += 256) {
        int k = i / D2, d = i % D2;
        ctx[k * 301 + d] = g_context[((size_t)b * KK + k) * D2 + d];
    }
    const int tt = tid >> 3, kk = tid & 7;
    for (int t0 = 0; t0 < TT; t0 += 32) {
        __syncthreads();
        for (int i = tid; i < 32 * D2; i += 256)
            seq_s[i] = g_seq[((size_t)b * TT + t0) * D2 + i];
        __syncthreads();
        if (kk < KK) {
            const float* sr = seq_s + tt * D2;
            const float* cr = ctx + kk * 301;
            float e = 0.f;
            #pragma unroll 4
            for (int d = 0; d < D2; d++) e += sr[d] * cr[d];
            g_energy[((size_t)b * TT + t0 + tt) * KK + kk] = e;
        }
    }
}

// ==========================================================================
// K3c: softmax over T per (b,k), in place on g_energy
// ==========================================================================
__global__ void __launch_bounds__(192) softmax_t()
{
    const int b = blockIdx.x;
    const int k = threadIdx.x >> 5;
    const int lane = threadIdx.x & 31;
    float v[16];
    float m = -1e30f;
    #pragma unroll
    for (int i = 0; i < 16; i++) {
        v[i] = g_energy[((size_t)b * TT + lane + i * 32) * KK + k];
        m = fmaxf(m, v[i]);
    }
    #pragma unroll
    for (int o = 16; o; o >>= 1) m = fmaxf(m, __shfl_xor_sync(0xffffffffu, m, o));
    float ssum = 0.f;
    #pragma unroll
    for (int i = 0; i < 16; i++) { v[i] = __expf(v[i] - m); ssum += v[i]; }
    #pragma unroll
    for (int o = 16; o; o >>= 1) ssum += __shfl_xor_sync(0xffffffffu, ssum, o);
    const float inv = 1.f / ssum;
    #pragma unroll
    for (int i = 0; i < 16; i++)
        g_energy[((size_t)b * TT + lane + i * 32) * KK + k] = v[i] * inv;
}

// ==========================================================================
// K3d: pooled[b][k][d] = sum_t seq[b,t,d] * probs[b,t,k]
// ==========================================================================
__global__ void __launch_bounds__(320) pooled_kernel()
{
    const int b = blockIdx.x;
    const int tid = threadIdx.x;
    __shared__ float seq_s[32 * D2];
    __shared__ float pr[32 * 8];
    float acc[KK];
    #pragma unroll
    for (int k = 0; k < KK; k++) acc[k] = 0.f;
    for (int t0 = 0; t0 < TT; t0 += 32) {
        __syncthreads();
        for (int i = tid; i < 32 * D2; i += 320)
            seq_s[i] = g_seq[((size_t)b * TT + t0) * D2 + i];
        for (int i = tid; i < 32 * KK; i += 320) {
            int tt = i / KK, k = i % KK;
            pr[tt * 8 + k] = g_energy[((size_t)b * TT + t0 + tt) * KK + k];
        }
        __syncthreads();
        if (tid < D2) {
            #pragma unroll 4
            for (int tt = 0; tt < 32; tt++) {
                const float sv = seq_s[tt * D2 + tid];
                #pragma unroll
                for (int k = 0; k < KK; k++) acc[k] += sv * pr[tt * 8 + k];
            }
        }
    }
    if (tid < D2) {
        #pragma unroll
        for (int k = 0; k < KK; k++)
            g_pooled[((size_t)b * KK + k) * D2 + tid] = acc[k];
    }
}

// ==========================================================================
// K3e: topic heads + logits + softmax + per-batch reg term
// ==========================================================================
__global__ void __launch_bounds__(128) head_kernel(
    const float* __restrict__ Wtop, const float* __restrict__ btop,
    const float* __restrict__ Wout, const float* __restrict__ bout,
    float* __restrict__ out)
{
    const int b = blockIdx.x;
    const int tid = threadIdx.x;
    __shared__ float pl[KK * D2];
    __shared__ float cx[KK * D2];
    __shared__ float tp[KK * THD];
    __shared__ float lg[CLSN];
    __shared__ float inorm[KK];
    __shared__ float gsq[KK * KK];
    for (int i = tid; i < KK * D2; i += 128) {
        pl[i] = g_pooled[(size_t)b * KK * D2 + i];
        cx[i] = g_context[(size_t)b * KK * D2 + i];
    }
    __syncthreads();
    if (tid < KK * THD) {
        const int k = tid / THD, h = tid % THD;
        float a = btop[tid];
        const float* pk = pl + k * D2;
        for (int d = 0; d < D2; d++)
            a += pk[d] * Wtop[((size_t)k * D2 + d) * THD + h];
        tp[tid] = fmaxf(a, 0.f);
    }
    if (tid >= 120 && tid < 120 + KK) {
        const int k = tid - 120;
        const float* ck = cx + k * D2;
        float s = 0.f;
        for (int d = 0; d < D2; d++) s += ck[d] * ck[d];
        inorm[k] = 1.f / fmaxf(sqrtf(s), 1e-12f);
    }
    __syncthreads();
    if (tid < CLSN) {
        float L = bout[tid];
        for (int i = 0; i < KK * THD; i++) L += tp[i] * Wout[i * CLSN + tid];
        lg[tid] = L;
    }
    if (tid >= 32 && tid < 32 + KK * KK) {
        const int q = tid - 32;
        const int k = q / KK, j = q % KK;
        const float* ck = cx + k * D2;
        const float* cj = cx + j * D2;
        float gdot = 0.f;
        for (int d = 0; d < D2; d++) gdot += ck[d] * cj[d];
        gdot *= inorm[k] * inorm[j];
        const float diff = gdot - (k == j ? 1.f : 0.f);
        gsq[q] = diff * diff;
    }
    __syncthreads();
    if (tid < CLSN) {
        float m = lg[0];
        #pragma unroll
        for (int i = 1; i < CLSN; i++) m = fmaxf(m, lg[i]);
        float ss = 0.f;
        #pragma unroll
        for (int i = 0; i < CLSN; i++) ss += __expf(lg[i] - m);
        out[b * CLSN + tid] = __expf(lg[tid] - m) / ss;
    }
    if (tid == 0) {
        float ssum = 0.f;
        #pragma unroll
        for (int i = 0; i < KK * KK; i++) ssum += gsq[i];
        g_regb[b] = sqrtf(ssum);
    }
}

// ==========================================================================
// K3f: reg = mean_b(g_regb)
// ==========================================================================
__global__ void __launch_bounds__(128) reg_reduce(float* __restrict__ out, int out_size)
{
    __shared__ float sh[128];
    const int tid = threadIdx.x;
    sh[tid] = g_regb[tid];
    __syncthreads();
    for (int o = 64; o; o >>= 1) {
        if (tid < o) sh[tid] += sh[tid + o];
        __syncthreads();
    }
    if (tid == 0) out[out_size - 1] = sh[0] * (1.f / 128.f);
}

// ==========================================================================
extern "C" void kernel_launch(void* const* d_in, const int* in_sizes, int n_in,
                              void* d_out, int out_size)
{
    const float* x            = (const float*)d_in[0];
    const float* Wih_f        = (const float*)d_in[1];
    const float* Whh_f        = (const float*)d_in[2];
    const float* bih_f        = (const float*)d_in[3];
    const float* bhh_f        = (const float*)d_in[4];
    const float* Wih_b        = (const float*)d_in[5];
    const float* Whh_b        = (const float*)d_in[6];
    const float* bih_b        = (const float*)d_in[7];
    const float* bhh_b        = (const float*)d_in[8];
    const float* attn_context = (const float*)d_in[9];
    const float* Wattn        = (const float*)d_in[10];
    const float* battn        = (const float*)d_in[11];
    const float* Wtop         = (const float*)d_in[12];
    const float* btop         = (const float*)d_in[13];
    const float* Wout         = (const float*)d_in[14];
    const float* bout         = (const float*)d_in[15];
    float* out = (float*)d_out;

    cudaFuncSetAttribute(gru_scan, cudaFuncAttributeMaxDynamicSharedMemorySize, GRU_SMEM);

    const size_t xtot = (size_t)BB * TT * KP;
    cvt_x<<<(unsigned)((xtot + 255) / 256), 256>>>(x);
    cvt_w<<<(NPAD * KP + 255) / 256, 256>>>(Wih_f, Wih_b);
    gi_gemm_mma<<<dim3((BB * TT) / GBM, NPAD / GBN), 256>>>(bih_f, bih_b);
    gru_scan<<<128, 512, GRU_SMEM>>>(Whh_f, Whh_b, bhh_f, bhh_b);
    ctxA_kernel<<<KK, 320>>>(attn_context, Wattn, battn);
    context_kernel<<<dim3(KK, 32), 320>>>(Wattn);
    energy_kernel<<<BB, 256>>>();
    softmax_t<<<BB, 192>>>();
    pooled_kernel<<<BB, 320>>>();
    head_kernel<<<BB, 128>>>(Wtop, btop, Wout, bout, out);
    reg_reduce<<<1, 128>>>(out, out_size);
}

// round 6
// speedup vs baseline: 1.6844x; 1.0743x over previous
#include <cuda_runtime.h>
#include <cuda_fp16.h>
#include <cstdint>
#include <cstddef>

// ---------------- problem constants ----------------
#define BB    128
#define TT    512
#define II    300
#define HH    150
#define G3    450    // 3H
#define D2    300    // 2H
#define KK    6
#define THD   20
#define CLSN  5

#define KP    320    // padded K for fp16 GEMM (300 -> 320)
#define NPAD  960    // padded N (900 -> 960)

// ---------------- device scratch (static, allocation-free) ----------------
__device__ float g_gi[(size_t)2 * BB * TT * G3];    // [dir][b][t][g]
__device__ float g_seq[(size_t)BB * TT * D2];       // [b][t][d]
__device__ float g_hidden[BB * D2];
__device__ float g_ctxA[KK * D2];
__device__ float g_context[BB * KK * D2];
__device__ float g_energy[(size_t)BB * TT * KK];    // energy, then probs in-place
__device__ float g_pooled[BB * KK * D2];
__device__ float g_regb[BB];
__device__ __half g_xh[(size_t)BB * TT * KP];       // fp16 x, K padded
__device__ __half g_wh[(size_t)NPAD * KP];          // fp16 [Wf;Wb], K padded

// ==========================================================================
// K0a/K0b: fp32 -> fp16 conversion (zero-padded K)
// ==========================================================================
__global__ void __launch_bounds__(256) cvt_x(const float* __restrict__ x)
{
    size_t i = (size_t)blockIdx.x * 256 + threadIdx.x;
    if (i >= (size_t)BB * TT * KP) return;
    int col = (int)(i % KP);
    size_t row = i / KP;
    g_xh[i] = (col < II) ? __float2half_rn(x[row * II + col]) : __float2half(0.f);
}

__global__ void __launch_bounds__(256) cvt_w(const float* __restrict__ Wf,
                                             const float* __restrict__ Wb)
{
    int i = blockIdx.x * 256 + threadIdx.x;
    if (i >= NPAD * KP) return;
    int col = i % KP;
    int row = i / KP;
    float v = 0.f;
    if (col < II && row < 900)
        v = (row < 450) ? Wf[row * II + col] : Wb[(row - 450) * II + col];
    g_wh[i] = __float2half_rn(v);
}

// ==========================================================================
// K1: gi GEMM on tensor cores (mma.sync m16n8k16, fp16 in / fp32 accum)
// ==========================================================================
__device__ __forceinline__ uint32_t s2u(const void* p) {
    return (uint32_t)__cvta_generic_to_shared(p);
}

#define LDSM4(R, addr) \
    asm volatile("ldmatrix.sync.aligned.m8n8.x4.shared.b16 {%0,%1,%2,%3}, [%4];" \
        : "=r"((R)[0]), "=r"((R)[1]), "=r"((R)[2]), "=r"((R)[3]) : "r"(addr))

#define MMA16816(C, A, b0, b1) \
    asm volatile("mma.sync.aligned.m16n8k16.row.col.f32.f16.f16.f32 " \
        "{%0,%1,%2,%3},{%4,%5,%6,%7},{%8,%9},{%0,%1,%2,%3};" \
        : "+f"((C)[0]), "+f"((C)[1]), "+f"((C)[2]), "+f"((C)[3]) \
        : "r"((A)[0]), "r"((A)[1]), "r"((A)[2]), "r"((A)[3]), "r"(b0), "r"(b1))

#define GBM 128
#define GBN 64
#define GBK 32
#define SPAD 40      // smem row stride in halves (80B: conflict-free ldmatrix)

__global__ void __launch_bounds__(256) gi_gemm_mma(
    const float* __restrict__ bf, const float* __restrict__ bb)
{
    __shared__ __half As[2][GBM][SPAD];
    __shared__ __half Bs[2][GBN][SPAD];

    const int tid  = threadIdx.x;
    const int m0   = blockIdx.x * GBM;
    const int n0   = blockIdx.y * GBN;
    const int warp = tid >> 5;
    const int lane = tid & 31;
    const int wm   = (warp >> 1) * 32;   // 0,32,64,96
    const int wn   = (warp & 1) * 32;    // 0,32

    const int gr = tid >> 2;            // 0..63
    const int gc = (tid & 3) * 8;       // half offset
    const __half* aP0 = g_xh + (size_t)(m0 + gr) * KP + gc;
    const __half* aP1 = g_xh + (size_t)(m0 + gr + 64) * KP + gc;
    const __half* bP  = g_wh + (size_t)(n0 + gr) * KP + gc;

    const uint32_t aAddr = s2u(&As[0][wm + (lane & 15)][(lane >> 4) * 8]);
    const uint32_t bAddr = s2u(&Bs[0][wn + ((lane >> 4) << 3) + (lane & 7)][((lane >> 3) & 1) * 8]);
    const uint32_t ABUF = GBM * SPAD * 2;   // 10240
    const uint32_t BBUF = GBN * SPAD * 2;   // 5120
    const uint32_t RSTR = SPAD * 2;         // 80 bytes / row

    float acc[2][4][4];
    #pragma unroll
    for (int i = 0; i < 2; i++)
        #pragma unroll
        for (int j = 0; j < 4; j++)
            #pragma unroll
            for (int q = 0; q < 4; q++) acc[i][j][q] = 0.f;

    uint4 ra0 = *(const uint4*)aP0;
    uint4 ra1 = *(const uint4*)aP1;
    uint4 rb  = *(const uint4*)bP;
    *(uint4*)&As[0][gr][gc]      = ra0;
    *(uint4*)&As[0][gr + 64][gc] = ra1;
    *(uint4*)&Bs[0][gr][gc]      = rb;
    __syncthreads();

    const int NKT = KP / GBK;   // 10
    for (int kt = 0; kt < NKT; kt++) {
        const int buf = kt & 1;
        if (kt < NKT - 1) {
            const size_t off = (size_t)(kt + 1) * GBK;
            ra0 = *(const uint4*)(aP0 + off);
            ra1 = *(const uint4*)(aP1 + off);
            rb  = *(const uint4*)(bP + off);
        }
        #pragma unroll
        for (int ks = 0; ks < 2; ks++) {
            uint32_t A0[4], A1[4], B0[4], B1[4];
            const uint32_t ao = aAddr + buf * ABUF + ks * 32;
            const uint32_t bo = bAddr + buf * BBUF + ks * 32;
            LDSM4(A0, ao);
            LDSM4(A1, ao + 16 * RSTR);
            LDSM4(B0, bo);
            LDSM4(B1, bo + 16 * RSTR);
            MMA16816(acc[0][0], A0, B0[0], B0[1]);
            MMA16816(acc[0][1], A0, B0[2], B0[3]);
            MMA16816(acc[0][2], A0, B1[0], B1[1]);
            MMA16816(acc[0][3], A0, B1[2], B1[3]);
            MMA16816(acc[1][0], A1, B0[0], B0[1]);
            MMA16816(acc[1][1], A1, B0[2], B0[3]);
            MMA16816(acc[1][2], A1, B1[0], B1[1]);
            MMA16816(acc[1][3], A1, B1[2], B1[3]);
        }
        if (kt < NKT - 1) {
            const int nb = buf ^ 1;
            *(uint4*)&As[nb][gr][gc]      = ra0;
            *(uint4*)&As[nb][gr + 64][gc] = ra1;
            *(uint4*)&Bs[nb][gr][gc]      = rb;
        }
        __syncthreads();
    }

    // epilogue: scatter to g_gi with bias
    const int cr = lane >> 2;           // row within 8
    const int cc = (lane & 3) * 2;      // col pair
    #pragma unroll
    for (int mi = 0; mi < 2; mi++) {
        #pragma unroll
        for (int ni = 0; ni < 4; ni++) {
            const int n = n0 + wn + ni * 8 + cc;
            if (n + 1 < 900) {
                const int dir = (n >= 450);
                const int g   = n - dir * 450;
                const float b0v = dir ? bb[g]     : bf[g];
                const float b1v = dir ? bb[g + 1] : bf[g + 1];
                const size_t dbase = (size_t)dir * BB * TT * G3;
                const int m = m0 + wm + mi * 16 + cr;
                float* p0 = g_gi + dbase + (size_t)m * G3 + g;
                float* p1 = g_gi + dbase + (size_t)(m + 8) * G3 + g;
                p0[0] = acc[mi][ni][0] + b0v;
                p0[1] = acc[mi][ni][1] + b1v;
                p1[0] = acc[mi][ni][2] + b0v;
                p1[1] = acc[mi][ni][3] + b1v;
            }
        }
    }
}

// ==========================================================================
// K2: GRU scan with REGISTER-RESIDENT weights.
//     128 CTAs, each owns (dir, batch-pair), 512 sequential steps.
//     Each of 450 matvec threads holds its Whh row as 76 half2 registers;
//     per-step smem traffic is only the broadcast h vector + ghm exchange.
// ==========================================================================
__global__ void __launch_bounds__(480, 1) gru_scan(
    const float* __restrict__ Whh_f, const float* __restrict__ Whh_b,
    const float* __restrict__ bhh_f, const float* __restrict__ bhh_b)
{
    __shared__ __align__(16) __half hh[2][152];   // fp16 h, 2 batches (+pad)
    __shared__ float hf[304];                     // fp32 master h
    __shared__ float ghm[2][452];                 // gh exchange

    const int tid = threadIdx.x;
    const int dir = blockIdx.x >> 6;
    const int b0  = (blockIdx.x & 63) * 2;

    // ---- one-time: load this thread's weight row into registers (fp16) ----
    __half2 w[76];
    float bhv = 0.f;
    if (tid < G3) {
        const float* Whh = (dir ? Whh_b : Whh_f) + tid * HH;
        #pragma unroll
        for (int q = 0; q < 75; q++)
            w[q] = __floats2half2_rn(Whh[2 * q], Whh[2 * q + 1]);
        w[75] = __floats2half2_rn(0.f, 0.f);
        bhv = (dir ? bhh_b : bhh_f)[tid];
    }
    for (int i = tid; i < 2 * 152; i += 480) hh[0][i] = __float2half(0.f);
    if (tid < 300) hf[tid] = 0.f;
    __syncthreads();

    const int nb = tid / HH;     // valid when tid < 300
    const int j  = tid - nb * HH;

    // strided pointers (avoid per-step muls)
    const long dstep = dir ? -(long)G3 : (long)G3;
    const long sstep = dir ? -(long)D2 : (long)D2;
    const int  t0    = dir ? (TT - 1) : 0;
    const float* gip = g_gi + (((size_t)(dir * BB + b0 + nb)) * TT + t0) * G3 + j;
    float*       sqp = g_seq + (((size_t)(b0 + nb)) * TT + t0) * D2 + dir * HH + j;

    for (int s = 0; s < TT; s++) {
        // issue gi loads early; consumed only after the matvec + barrier
        float gir = 0.f, giz = 0.f, gin = 0.f;
        if (tid < 300) {
            gir = gip[0]; giz = gip[HH]; gin = gip[2 * HH];
        }
        if (tid < G3) {
            const uint4* h0 = (const uint4*)hh[0];
            const uint4* h1 = (const uint4*)hh[1];
            float acc0 = 0.f, acc1 = 0.f;
            #pragma unroll
            for (int c = 0; c < 19; c++) {
                uint4 ha = h0[c];                  // broadcast LDS.128
                uint4 hb = h1[c];
                const __half2* hap = (const __half2*)&ha;
                const __half2* hbp = (const __half2*)&hb;
                __half2 s0 = __floats2half2_rn(0.f, 0.f);
                __half2 s1 = s0;
                #pragma unroll
                for (int q = 0; q < 4; q++) {
                    s0 = __hfma2(w[c * 4 + q], hap[q], s0);
                    s1 = __hfma2(w[c * 4 + q], hbp[q], s1);
                }
                float2 f0 = __half22float2(s0); acc0 += f0.x + f0.y;
                float2 f1 = __half22float2(s1); acc1 += f1.x + f1.y;
            }
            ghm[0][tid] = acc0 + bhv;
            ghm[1][tid] = acc1 + bhv;
        }
        __syncthreads();
        if (tid < 300) {
            const float* gh = ghm[nb];
            float r = 1.f / (1.f + __expf(-(gir + gh[j])));
            float z = 1.f / (1.f + __expf(-(giz + gh[HH + j])));
            float n = tanhf(gin + r * gh[2 * HH + j]);
            float h = hf[tid];
            float hn = (1.f - z) * n + z * h;
            hf[tid] = hn;
            hh[nb][j] = __float2half_rn(hn);
            *sqp = hn;
            gip += dstep;
            sqp += sstep;
        }
        __syncthreads();
    }
    if (tid < 300)
        g_hidden[(b0 + nb) * D2 + dir * HH + j] = hf[tid];
}

// ==========================================================================
// K3a0: ctxA[k][d] = battn[k][d] + attn_context[k,:] . Wattn[k][:300][d]
// ==========================================================================
__global__ void __launch_bounds__(320) ctxA_kernel(
    const float* __restrict__ attn_context, const float* __restrict__ Wattn,
    const float* __restrict__ battn)
{
    const int k = blockIdx.x;
    const int d = threadIdx.x;
    __shared__ float ac[D2];
    if (d < D2) ac[d] = attn_context[k * D2 + d];
    __syncthreads();
    if (d < D2) {
        float acc = battn[k * D2 + d];
        const float* wp = Wattn + (size_t)k * 600 * D2 + d;
        #pragma unroll 1
        for (int c = 0; c < D2; c += 4) {
            float w0 = wp[(size_t)(c + 0) * D2];
            float w1 = wp[(size_t)(c + 1) * D2];
            float w2 = wp[(size_t)(c + 2) * D2];
            float w3 = wp[(size_t)(c + 3) * D2];
            acc += ac[c] * w0 + ac[c + 1] * w1 + ac[c + 2] * w2 + ac[c + 3] * w3;
        }
        g_ctxA[k * D2 + d] = acc;
    }
}

// ==========================================================================
// K3a: context[b][k][d] = tanh(ctxA[k][d] + hidden[b,:] . Wattn[k][300:][d])
// ==========================================================================
__global__ void __launch_bounds__(320) context_kernel(const float* __restrict__ Wattn)
{
    const int k  = blockIdx.x;
    const int b0 = blockIdx.y * 4;
    const int d  = threadIdx.x;
    __shared__ float hid[4 * D2];
    for (int i = threadIdx.x; i < 4 * D2; i += blockDim.x) hid[i] = g_hidden[b0 * D2 + i];
    __syncthreads();
    if (d < D2) {
        float acc[4];
        const float base = g_ctxA[k * D2 + d];
        #pragma unroll
        for (int bb = 0; bb < 4; bb++) acc[bb] = base;
        const float* wp = Wattn + ((size_t)k * 600 + D2) * D2 + d;
        #pragma unroll 1
        for (int jj = 0; jj < D2; jj += 4) {
            float w0 = wp[(size_t)(jj + 0) * D2];
            float w1 = wp[(size_t)(jj + 1) * D2];
            float w2 = wp[(size_t)(jj + 2) * D2];
            float w3 = wp[(size_t)(jj + 3) * D2];
            #pragma unroll
            for (int bb = 0; bb < 4; bb++) {
                acc[bb] += hid[bb * D2 + jj] * w0 + hid[bb * D2 + jj + 1] * w1
                         + hid[bb * D2 + jj + 2] * w2 + hid[bb * D2 + jj + 3] * w3;
            }
        }
        #pragma unroll
        for (int bb = 0; bb < 4; bb++)
            g_context[((size_t)(b0 + bb) * KK + k) * D2 + d] = tanhf(acc[bb]);
    }
}

// ==========================================================================
// K3b: energy[b][t][k] = seq[b,t,:] . context[b,k,:]
// ==========================================================================
__global__ void __launch_bounds__(256) energy_kernel()
{
    const int b = blockIdx.x;
    __shared__ float ctx[KK * 301];
    __shared__ float seq_s[32 * D2];
    const int tid = threadIdx.x;
    for (int i = tid; i < KK * D2; i += 256) {
        int k = i / D2, d = i % D2;
        ctx[k * 301 + d] = g_context[((size_t)b * KK + k) * D2 + d];
    }
    const int tt = tid >> 3, kk = tid & 7;
    for (int t0 = 0; t0 < TT; t0 += 32) {
        __syncthreads();
        for (int i = tid; i < 32 * D2; i += 256)
            seq_s[i] = g_seq[((size_t)b * TT + t0) * D2 + i];
        __syncthreads();
        if (kk < KK) {
            const float* sr = seq_s + tt * D2;
            const float* cr = ctx + kk * 301;
            float e = 0.f;
            #pragma unroll 4
            for (int d = 0; d < D2; d++) e += sr[d] * cr[d];
            g_energy[((size_t)b * TT + t0 + tt) * KK + kk] = e;
        }
    }
}

// ==========================================================================
// K3c: softmax over T per (b,k), in place on g_energy
// ==========================================================================
__global__ void __launch_bounds__(192) softmax_t()
{
    const int b = blockIdx.x;
    const int k = threadIdx.x >> 5;
    const int lane = threadIdx.x & 31;
    float v[16];
    float m = -1e30f;
    #pragma unroll
    for (int i = 0; i < 16; i++) {
        v[i] = g_energy[((size_t)b * TT + lane + i * 32) * KK + k];
        m = fmaxf(m, v[i]);
    }
    #pragma unroll
    for (int o = 16; o; o >>= 1) m = fmaxf(m, __shfl_xor_sync(0xffffffffu, m, o));
    float ssum = 0.f;
    #pragma unroll
    for (int i = 0; i < 16; i++) { v[i] = __expf(v[i] - m); ssum += v[i]; }
    #pragma unroll
    for (int o = 16; o; o >>= 1) ssum += __shfl_xor_sync(0xffffffffu, ssum, o);
    const float inv = 1.f / ssum;
    #pragma unroll
    for (int i = 0; i < 16; i++)
        g_energy[((size_t)b * TT + lane + i * 32) * KK + k] = v[i] * inv;
}

// ==========================================================================
// K3d: pooled[b][k][d] = sum_t seq[b,t,d] * probs[b,t,k]
// ==========================================================================
__global__ void __launch_bounds__(320) pooled_kernel()
{
    const int b = blockIdx.x;
    const int tid = threadIdx.x;
    __shared__ float seq_s[32 * D2];
    __shared__ float pr[32 * 8];
    float acc[KK];
    #pragma unroll
    for (int k = 0; k < KK; k++) acc[k] = 0.f;
    for (int t0 = 0; t0 < TT; t0 += 32) {
        __syncthreads();
        for (int i = tid; i < 32 * D2; i += 320)
            seq_s[i] = g_seq[((size_t)b * TT + t0) * D2 + i];
        for (int i = tid; i < 32 * KK; i += 320) {
            int tt = i / KK, k = i % KK;
            pr[tt * 8 + k] = g_energy[((size_t)b * TT + t0 + tt) * KK + k];
        }
        __syncthreads();
        if (tid < D2) {
            #pragma unroll 4
            for (int tt = 0; tt < 32; tt++) {
                const float sv = seq_s[tt * D2 + tid];
                #pragma unroll
                for (int k = 0; k < KK; k++) acc[k] += sv * pr[tt * 8 + k];
            }
        }
    }
    if (tid < D2) {
        #pragma unroll
        for (int k = 0; k < KK; k++)
            g_pooled[((size_t)b * KK + k) * D2 + tid] = acc[k];
    }
}

// ==========================================================================
// K3e: topic heads + logits + softmax + per-batch reg term
// ==========================================================================
__global__ void __launch_bounds__(128) head_kernel(
    const float* __restrict__ Wtop, const float* __restrict__ btop,
    const float* __restrict__ Wout, const float* __restrict__ bout,
    float* __restrict__ out)
{
    const int b = blockIdx.x;
    const int tid = threadIdx.x;
    __shared__ float pl[KK * D2];
    __shared__ float cx[KK * D2];
    __shared__ float tp[KK * THD];
    __shared__ float lg[CLSN];
    __shared__ float inorm[KK];
    __shared__ float gsq[KK * KK];
    for (int i = tid; i < KK * D2; i += 128) {
        pl[i] = g_pooled[(size_t)b * KK * D2 + i];
        cx[i] = g_context[(size_t)b * KK * D2 + i];
    }
    __syncthreads();
    if (tid < KK * THD) {
        const int k = tid / THD, h = tid % THD;
        float a = btop[tid];
        const float* pk = pl + k * D2;
        for (int d = 0; d < D2; d++)
            a += pk[d] * Wtop[((size_t)k * D2 + d) * THD + h];
        tp[tid] = fmaxf(a, 0.f);
    }
    if (tid >= 120 && tid < 120 + KK) {
        const int k = tid - 120;
        const float* ck = cx + k * D2;
        float s = 0.f;
        for (int d = 0; d < D2; d++) s += ck[d] * ck[d];
        inorm[k] = 1.f / fmaxf(sqrtf(s), 1e-12f);
    }
    __syncthreads();
    if (tid < CLSN) {
        float L = bout[tid];
        for (int i = 0; i < KK * THD; i++) L += tp[i] * Wout[i * CLSN + tid];
        lg[tid] = L;
    }
    if (tid >= 32 && tid < 32 + KK * KK) {
        const int q = tid - 32;
        const int k = q / KK, j = q % KK;
        const float* ck = cx + k * D2;
        const float* cj = cx + j * D2;
        float gdot = 0.f;
        for (int d = 0; d < D2; d++) gdot += ck[d] * cj[d];
        gdot *= inorm[k] * inorm[j];
        const float diff = gdot - (k == j ? 1.f : 0.f);
        gsq[q] = diff * diff;
    }
    __syncthreads();
    if (tid < CLSN) {
        float m = lg[0];
        #pragma unroll
        for (int i = 1; i < CLSN; i++) m = fmaxf(m, lg[i]);
        float ss = 0.f;
        #pragma unroll
        for (int i = 0; i < CLSN; i++) ss += __expf(lg[i] - m);
        out[b * CLSN + tid] = __expf(lg[tid] - m) / ss;
    }
    if (tid == 0) {
        float ssum = 0.f;
        #pragma unroll
        for (int i = 0; i < KK * KK; i++) ssum += gsq[i];
        g_regb[b] = sqrtf(ssum);
    }
}

// ==========================================================================
// K3f: reg = mean_b(g_regb)
// ==========================================================================
__global__ void __launch_bounds__(128) reg_reduce(float* __restrict__ out, int out_size)
{
    __shared__ float sh[128];
    const int tid = threadIdx.x;
    sh[tid] = g_regb[tid];
    __syncthreads();
    for (int o = 64; o; o >>= 1) {
        if (tid < o) sh[tid] += sh[tid + o];
        __syncthreads();
    }
    if (tid == 0) out[out_size - 1] = sh[0] * (1.f / 128.f);
}

// ==========================================================================
extern "C" void kernel_launch(void* const* d_in, const int* in_sizes, int n_in,
                              void* d_out, int out_size)
{
    const float* x            = (const float*)d_in[0];
    const float* Wih_f        = (const float*)d_in[1];
    const float* Whh_f        = (const float*)d_in[2];
    const float* bih_f        = (const float*)d_in[3];
    const float* bhh_f        = (const float*)d_in[4];
    const float* Wih_b        = (const float*)d_in[5];
    const float* Whh_b        = (const float*)d_in[6];
    const float* bih_b        = (const float*)d_in[7];
    const float* bhh_b        = (const float*)d_in[8];
    const float* attn_context = (const float*)d_in[9];
    const float* Wattn        = (const float*)d_in[10];
    const float* battn        = (const float*)d_in[11];
    const float* Wtop         = (const float*)d_in[12];
    const float* btop         = (const float*)d_in[13];
    const float* Wout         = (const float*)d_in[14];
    const float* bout         = (const float*)d_in[15];
    float* out = (float*)d_out;

    const size_t xtot = (size_t)BB * TT * KP;
    cvt_x<<<(unsigned)((xtot + 255) / 256), 256>>>(x);
    cvt_w<<<(NPAD * KP + 255) / 256, 256>>>(Wih_f, Wih_b);
    gi_gemm_mma<<<dim3((BB * TT) / GBM, NPAD / GBN), 256>>>(bih_f, bih_b);
    gru_scan<<<128, 480>>>(Whh_f, Whh_b, bhh_f, bhh_b);
    ctxA_kernel<<<KK, 320>>>(attn_context, Wattn, battn);
    context_kernel<<<dim3(KK, 32), 320>>>(Wattn);
    energy_kernel<<<BB, 256>>>();
    softmax_t<<<BB, 192>>>();
    pooled_kernel<<<BB, 320>>>();
    head_kernel<<<BB, 128>>>(Wtop, btop, Wout, bout, out);
    reg_reduce<<<1, 128>>>(out, out_size);
}